// round 15
// baseline (speedup 1.0000x reference)
#include <cuda_runtime.h>
#include <cuda_bf16.h>
#include <cstdint>
#include <cstddef>

#define DIN 1024
#define DOUT 1024

// ---------------- GEMM tiling ----------------
#define BM 128
#define BN 128
#define BK 64                 // 64 bf16 = 128B rows (SW128)
#define NSTAGE 3
#define KITERS (DIN / BK)     // 16
#define THREADS 256
#define A_BYTES (BM * 128)    // 16384
#define B_BYTES (BN * 128)    // 16384
#define STAGE_BYTES (A_BYTES + B_BYTES)        // 32768
#define SMEM_TOTAL (NSTAGE * STAGE_BYTES)      // 98304

// Scratch (allocation-free rule: __device__ globals)
__device__ __nv_bfloat16 g_xq[8u * 8192u * 1024u];
__device__ __nv_bfloat16 g_wq[(size_t)DOUT * DIN];

// ============================ fake-quant kernel ============================
// Warp-coalesced, bit-exact MXFP fake-quant (block=32, EMAX=8, 6-bit mantissa,
// round-half-away, clip +-448), done directly in the ORIGINAL domain
// (power-of-2 scale commutes with mantissa rounding). 8 float4 per thread,
// all loads front-batched (MLP=8). One launch covers x then w.
__global__ void __launch_bounds__(256) quant_fused_kernel(
        const float4* __restrict__ xin, uint2* __restrict__ xout,
        const float4* __restrict__ win, uint2* __restrict__ wout, int xwarps) {
    int gw = (blockIdx.x * blockDim.x + threadIdx.x) >> 5;   // global warp id
    int lane = threadIdx.x & 31;

    const float4* in;
    uint2* out;
    int base;
    if (gw < xwarps) {
        in = xin; out = xout; base = gw * 256 + lane;
    } else {
        in = win; out = wout; base = (gw - xwarps) * 256 + lane;
    }

    float4 v4[8];
#pragma unroll
    for (int j = 0; j < 8; j++) v4[j] = in[base + 32 * j];   // coalesced, MLP=8

#pragma unroll
    for (int j = 0; j < 8; j++) {
        float4 t = v4[j];
        float amax = fmaxf(fmaxf(fabsf(t.x), fabsf(t.y)),
                           fmaxf(fabsf(t.z), fabsf(t.w)));
        amax = fmaxf(amax, __shfl_xor_sync(0xFFFFFFFFu, amax, 1));
        amax = fmaxf(amax, __shfl_xor_sync(0xFFFFFFFFu, amax, 2));
        amax = fmaxf(amax, __shfl_xor_sync(0xFFFFFFFFu, amax, 4));

        int ex = (__float_as_int(amax) >> 23) & 0xFF;
        int se = ex - 135;                       // floor(log2(amax)) - 8
        float e[4] = {t.x, t.y, t.z, t.w};
        float r[4];

        if (ex >= 26 && ex <= 245) {             // hot: se in [-109, 110]
            // block constants, all built from exponent bits
            float clip = __int_as_float(((se + 135) << 23) | 0x00600000); // 448*2^se
            float s1   = __int_as_float((139 - se) << 23);               // 2^(12-se)
            float s2   = __int_as_float((se + 115) << 23);               // 2^(se-12)
            int  thr   = (se + 121) << 23;                               // bits(2^(se-6))
#pragma unroll
            for (int i = 0; i < 4; i++) {
                int b  = __float_as_int(e[i]);
                int ab = b & 0x7FFFFFFF;
                // pexp unclamped: round-half-away to 6 mantissa bits + clip
                float q1 = fminf(__int_as_float((ab + 0x10000) & 0x7FFE0000), clip);
                // pexp clamped to se-6: fixed-point step 2^(se-12)
                float q2 = floorf(fmaf(__int_as_float(ab), s1, 0.5f)) * s2;
                float q  = (ab >= thr) ? q1 : q2;
                r[i] = __int_as_float(__float_as_int(q) | (b & 0x80000000));
            }
        } else {                                  // cold: exact reference math
            int fl = (ex != 0) ? (ex - 127) : ((amax == 0.f) ? -126 : ilogbf(amax));
            int sec = fl - 8;
            if (sec < -127) sec = -127;
            float scale = ldexpf(1.f, sec), inv_scale = ldexpf(1.f, -sec);
#pragma unroll
            for (int i = 0; i < 4; i++) {
                float vv = e[i] * inv_scale;
                float av = fabsf(vv);
                float q;
                if (av == 0.f) q = 0.f;
                else {
                    int pe = ilogbf(av);
                    if (pe < -6) pe = -6;
                    float stp = ldexpf(1.f, pe - 6);
                    float rr = floorf(fmaf(av, ldexpf(1.f, 6 - pe), 0.5f));
                    q = fminf(rr * stp, 448.f);
                }
                r[i] = copysignf(q, vv) * scale;
            }
        }
        uint2 o;
        asm("cvt.rn.bf16x2.f32 %0, %1, %2;" : "=r"(o.x) : "f"(r[1]), "f"(r[0]));
        asm("cvt.rn.bf16x2.f32 %0, %1, %2;" : "=r"(o.y) : "f"(r[3]), "f"(r[2]));
        out[base + 32 * j] = o;                    // coalesced 8B stores
    }
}

// ============================ PTX helpers ============================
__device__ __forceinline__ uint32_t smem_u32(const void* p) {
    return (uint32_t)__cvta_generic_to_shared(p);
}
#define SW128(o) ((o) ^ (((o) >> 3) & 0x70))

__device__ __forceinline__ void cp16(uint32_t dst, const void* src) {
    asm volatile("cp.async.cg.shared.global [%0], [%1], 16;" :: "r"(dst), "l"(src));
}
__device__ __forceinline__ void ldsm4(uint32_t& r0, uint32_t& r1, uint32_t& r2,
                                      uint32_t& r3, uint32_t a) {
    asm volatile("ldmatrix.sync.aligned.m8n8.x4.shared.b16 {%0,%1,%2,%3}, [%4];"
                 : "=r"(r0), "=r"(r1), "=r"(r2), "=r"(r3) : "r"(a));
}
__device__ __forceinline__ void mma16816(float* c, const uint32_t* a,
                                         const uint32_t* b) {
    asm volatile(
        "mma.sync.aligned.m16n8k16.row.col.f32.bf16.bf16.f32 "
        "{%0,%1,%2,%3}, {%4,%5,%6,%7}, {%8,%9}, {%0,%1,%2,%3};"
        : "+f"(c[0]), "+f"(c[1]), "+f"(c[2]), "+f"(c[3])
        : "r"(a[0]), "r"(a[1]), "r"(a[2]), "r"(a[3]), "r"(b[0]), "r"(b[1]));
}

// ============================ GEMM kernel ============================
// A = xq [M, K] row-major, B = wq [N, K] row-major (both K contiguous)
// out[m][n] = sum_k A[m][k]*B[n][k] + bias[n]
// CTA 128x128, 8 warps as 4(m) x 2(n), warp tile 32x64.
// (Proven config: 128 regs, 2 CTAs/SM, tensor pipe 70% — DO NOT PERTURB.)
__global__ void __launch_bounds__(THREADS)
gemm_kernel(const __nv_bfloat16* __restrict__ A, const __nv_bfloat16* __restrict__ Bw,
            const float* __restrict__ bias, float* __restrict__ out) {
    extern __shared__ __align__(1024) char smem[];
    uint32_t sb = smem_u32(smem);
    int tid = threadIdx.x, wid = tid >> 5, lid = tid & 31;
    int n0 = blockIdx.x * BN;
    int m0 = blockIdx.y * BM;
    int wm = wid & 3;          // 4 warp rows (32 each)
    int wn = wid >> 2;         // 2 warp cols (64 each)

    int laneA_row  = (lid & 7) + ((lid >> 3) & 1) * 8;   // 0..15
    int laneA_koff = (lid >> 4) * 16;                    // 0 or 16 bytes
    int laneB_row  = (lid & 7) + (lid >> 4) * 8;         // 0..15
    int laneB_koff = ((lid >> 3) & 1) * 16;              // 0 or 16 bytes

    float c[2][8][4];
#pragma unroll
    for (int t = 0; t < 2; t++)
#pragma unroll
        for (int q = 0; q < 8; q++)
#pragma unroll
            for (int j = 0; j < 4; j++) c[t][q][j] = 0.f;

    auto load_stage = [&](int buf, int kc) {
        uint32_t abase = sb + buf * STAGE_BYTES;
        uint32_t bbase = abase + A_BYTES;
        int k0 = kc * BK;
#pragma unroll
        for (int t = 0; t < 4; t++) {
            int idx = t * THREADS + tid;
            int r = idx >> 3, j = idx & 7;
            cp16(abase + SW128(r * 128 + j * 16),
                 A + (size_t)(m0 + r) * DIN + k0 + j * 8);
        }
#pragma unroll
        for (int t = 0; t < 4; t++) {
            int idx = t * THREADS + tid;
            int r = idx >> 3, j = idx & 7;
            cp16(bbase + SW128(r * 128 + j * 16),
                 Bw + (size_t)(n0 + r) * DIN + k0 + j * 8);
        }
        asm volatile("cp.async.commit_group;" ::: "memory");
    };

    load_stage(0, 0);
    load_stage(1, 1);

    for (int i = 0; i < KITERS; i++) {
        int buf = i % NSTAGE;
        if (i < KITERS - 1)
            asm volatile("cp.async.wait_group 1;" ::: "memory");
        else
            asm volatile("cp.async.wait_group 0;" ::: "memory");
        __syncthreads();

        if (i + 2 < KITERS) load_stage((i + 2) % NSTAGE, i + 2);

        uint32_t aS = sb + buf * STAGE_BYTES;
        uint32_t bS = aS + A_BYTES;
#pragma unroll
        for (int kk = 0; kk < 4; kk++) {
            uint32_t afrag[2][4];
#pragma unroll
            for (int t = 0; t < 2; t++) {
                int row = wm * 32 + t * 16 + laneA_row;
                ldsm4(afrag[t][0], afrag[t][1], afrag[t][2], afrag[t][3],
                      aS + SW128(row * 128 + kk * 32 + laneA_koff));
            }
#pragma unroll
            for (int p = 0; p < 4; p++) {
                int row = wn * 64 + p * 16 + laneB_row;
                uint32_t r0, r1, r2, r3;
                ldsm4(r0, r1, r2, r3,
                      bS + SW128(row * 128 + kk * 32 + laneB_koff));
                uint32_t b0[2] = {r0, r1}, b1[2] = {r2, r3};
#pragma unroll
                for (int t = 0; t < 2; t++) {
                    mma16816(c[t][2 * p], afrag[t], b0);
                    mma16816(c[t][2 * p + 1], afrag[t], b1);
                }
            }
        }
    }

    // ---- epilogue: fused bias + float2 stores ----
    int ncol0 = n0 + wn * 64 + (lid & 3) * 2;
    float2 bb[8];
#pragma unroll
    for (int q = 0; q < 8; q++)
        bb[q] = *reinterpret_cast<const float2*>(bias + ncol0 + q * 8);

#pragma unroll
    for (int t = 0; t < 2; t++) {
#pragma unroll
        for (int h = 0; h < 2; h++) {
            int m = m0 + wm * 32 + t * 16 + h * 8 + (lid >> 2);
            float* orow = out + (size_t)m * DOUT;
#pragma unroll
            for (int q = 0; q < 8; q++) {
                float2 vo;
                vo.x = c[t][q][2 * h + 0] + bb[q].x;
                vo.y = c[t][q][2 * h + 1] + bb[q].y;
                *reinterpret_cast<float2*>(orow + ncol0 + q * 8) = vo;
            }
        }
    }
}

// ============================ launch ============================
extern "C" void kernel_launch(void* const* d_in, const int* in_sizes, int n_in,
                              void* d_out, int out_size) {
    const float* x    = (const float*)d_in[0];
    const float* w    = (const float*)d_in[1];
    const float* bias = (const float*)d_in[2];
    float* out = (float*)d_out;
    int M = in_sizes[0] / DIN;   // 65536

    __nv_bfloat16 *xq, *wq;
    cudaGetSymbolAddress((void**)&xq, g_xq);
    cudaGetSymbolAddress((void**)&wq, g_wq);

    // single fused quant launch: x warps first, then w warps (256 float4/warp)
    int xwarps = (M * DIN / 4) / 256;          // 65536
    int wwarps = (DOUT * DIN / 4) / 256;       // 1024
    int qblocks = (xwarps + wwarps) / 8;       // 8 warps per 256-thr block
    quant_fused_kernel<<<qblocks, 256>>>((const float4*)x, (uint2*)xq,
                                         (const float4*)w, (uint2*)wq, xwarps);

    cudaFuncSetAttribute(gemm_kernel, cudaFuncAttributeMaxDynamicSharedMemorySize,
                         SMEM_TOTAL);
    dim3 grid(DOUT / BN, M / BM);   // (8, 512)
    gemm_kernel<<<grid, THREADS, SMEM_TOTAL>>>(xq, wq, bias, out);
}

// round 16
// speedup vs baseline: 1.0009x; 1.0009x over previous
#include <cuda_runtime.h>
#include <cuda_bf16.h>
#include <cstdint>
#include <cstddef>

#define DIN 1024
#define DOUT 1024

// ---------------- GEMM tiling ----------------
#define BM 128
#define BN 128
#define BK 64                 // 64 bf16 = 128B rows (SW128)
#define NSTAGE 3
#define KITERS (DIN / BK)     // 16
#define THREADS 256
#define A_BYTES (BM * 128)    // 16384
#define B_BYTES (BN * 128)    // 16384
#define STAGE_BYTES (A_BYTES + B_BYTES)        // 32768
#define SMEM_TOTAL (NSTAGE * STAGE_BYTES)      // 98304

// Scratch (allocation-free rule: __device__ globals)
__device__ __nv_bfloat16 g_xq[8u * 8192u * 1024u];
__device__ __nv_bfloat16 g_wq[(size_t)DOUT * DIN];

// ============================ fake-quant kernel ============================
// Warp-coalesced, bit-exact MXFP fake-quant (block=32, EMAX=8, 6-bit mantissa,
// round-half-away, clip +-448). Quantization done directly in the ORIGINAL
// domain (power-of-2 scale commutes with mantissa rounding). One fused launch
// covers both x (first xwarps warps) and w (remaining warps).
__global__ void __launch_bounds__(256) quant_fused_kernel(
        const float4* __restrict__ xin, uint2* __restrict__ xout,
        const float4* __restrict__ win, uint2* __restrict__ wout, int xwarps) {
    int gw = (blockIdx.x * blockDim.x + threadIdx.x) >> 5;   // global warp id
    int lane = threadIdx.x & 31;

    const float4* in;
    uint2* out;
    int base;
    if (gw < xwarps) {
        in = xin; out = xout; base = gw * 128 + lane;
    } else {
        in = win; out = wout; base = (gw - xwarps) * 128 + lane;
    }

    float4 v4[4];
#pragma unroll
    for (int j = 0; j < 4; j++) v4[j] = in[base + 32 * j];   // coalesced, MLP=4

#pragma unroll
    for (int j = 0; j < 4; j++) {
        float4 t = v4[j];
        float amax = fmaxf(fmaxf(fabsf(t.x), fabsf(t.y)),
                           fmaxf(fabsf(t.z), fabsf(t.w)));
        amax = fmaxf(amax, __shfl_xor_sync(0xFFFFFFFFu, amax, 1));
        amax = fmaxf(amax, __shfl_xor_sync(0xFFFFFFFFu, amax, 2));
        amax = fmaxf(amax, __shfl_xor_sync(0xFFFFFFFFu, amax, 4));

        int ex = (__float_as_int(amax) >> 23) & 0xFF;
        int se = ex - 135;                       // floor(log2(amax)) - 8
        float e[4] = {t.x, t.y, t.z, t.w};
        float r[4];

        if (ex >= 26 && ex <= 245) {             // hot: se in [-109, 110]
            // block constants, all built from exponent bits
            float clip = __int_as_float(((se + 135) << 23) | 0x00600000); // 448*2^se
            float s1   = __int_as_float((139 - se) << 23);               // 2^(12-se)
            float s2   = __int_as_float((se + 115) << 23);               // 2^(se-12)
            int  thr   = (se + 121) << 23;                               // bits(2^(se-6))
#pragma unroll
            for (int i = 0; i < 4; i++) {
                int b  = __float_as_int(e[i]);
                int ab = b & 0x7FFFFFFF;
                // pexp unclamped: round-half-away to 6 mantissa bits + clip
                float q1 = fminf(__int_as_float((ab + 0x10000) & 0x7FFE0000), clip);
                // pexp clamped to se-6: fixed-point step 2^(se-12)
                float q2 = floorf(fmaf(__int_as_float(ab), s1, 0.5f)) * s2;
                float q  = (ab >= thr) ? q1 : q2;
                r[i] = __int_as_float(__float_as_int(q) | (b & 0x80000000));
            }
        } else {                                  // cold: exact reference math
            int fl = (ex != 0) ? (ex - 127) : ((amax == 0.f) ? -126 : ilogbf(amax));
            int sec = fl - 8;
            if (sec < -127) sec = -127;
            float scale = ldexpf(1.f, sec), inv_scale = ldexpf(1.f, -sec);
#pragma unroll
            for (int i = 0; i < 4; i++) {
                float vv = e[i] * inv_scale;
                float av = fabsf(vv);
                float q;
                if (av == 0.f) q = 0.f;
                else {
                    int pe = ilogbf(av);
                    if (pe < -6) pe = -6;
                    float stp = ldexpf(1.f, pe - 6);
                    float rr = floorf(fmaf(av, ldexpf(1.f, 6 - pe), 0.5f));
                    q = fminf(rr * stp, 448.f);
                }
                r[i] = copysignf(q, vv) * scale;
            }
        }
        uint2 o;
        asm("cvt.rn.bf16x2.f32 %0, %1, %2;" : "=r"(o.x) : "f"(r[1]), "f"(r[0]));
        asm("cvt.rn.bf16x2.f32 %0, %1, %2;" : "=r"(o.y) : "f"(r[3]), "f"(r[2]));
        out[base + 32 * j] = o;                    // coalesced 8B stores
    }
}

// ============================ PTX helpers ============================
__device__ __forceinline__ uint32_t smem_u32(const void* p) {
    return (uint32_t)__cvta_generic_to_shared(p);
}
#define SW128(o) ((o) ^ (((o) >> 3) & 0x70))

__device__ __forceinline__ void cp16(uint32_t dst, const void* src) {
    asm volatile("cp.async.cg.shared.global [%0], [%1], 16;" :: "r"(dst), "l"(src));
}
__device__ __forceinline__ void ldsm4(uint32_t& r0, uint32_t& r1, uint32_t& r2,
                                      uint32_t& r3, uint32_t a) {
    asm volatile("ldmatrix.sync.aligned.m8n8.x4.shared.b16 {%0,%1,%2,%3}, [%4];"
                 : "=r"(r0), "=r"(r1), "=r"(r2), "=r"(r3) : "r"(a));
}
__device__ __forceinline__ void mma16816(float* c, const uint32_t* a,
                                         const uint32_t* b) {
    asm volatile(
        "mma.sync.aligned.m16n8k16.row.col.f32.bf16.bf16.f32 "
        "{%0,%1,%2,%3}, {%4,%5,%6,%7}, {%8,%9}, {%0,%1,%2,%3};"
        : "+f"(c[0]), "+f"(c[1]), "+f"(c[2]), "+f"(c[3])
        : "r"(a[0]), "r"(a[1]), "r"(a[2]), "r"(a[3]), "r"(b[0]), "r"(b[1]));
}

// ============================ GEMM kernel ============================
// A = xq [M, K] row-major, B = wq [N, K] row-major (both K contiguous)
// out[m][n] = sum_k A[m][k]*B[n][k] + bias[n]
// CTA 128x128, 8 warps as 4(m) x 2(n), warp tile 32x64.
// (Converged config: 128 regs = exact 2-CTA/SM budget, tensor pipe 70%.)
__global__ void __launch_bounds__(THREADS)
gemm_kernel(const __nv_bfloat16* __restrict__ A, const __nv_bfloat16* __restrict__ Bw,
            const float* __restrict__ bias, float* __restrict__ out) {
    extern __shared__ __align__(1024) char smem[];
    uint32_t sb = smem_u32(smem);
    int tid = threadIdx.x, wid = tid >> 5, lid = tid & 31;
    int n0 = blockIdx.x * BN;
    int m0 = blockIdx.y * BM;
    int wm = wid & 3;          // 4 warp rows (32 each)
    int wn = wid >> 2;         // 2 warp cols (64 each)

    int laneA_row  = (lid & 7) + ((lid >> 3) & 1) * 8;   // 0..15
    int laneA_koff = (lid >> 4) * 16;                    // 0 or 16 bytes
    int laneB_row  = (lid & 7) + (lid >> 4) * 8;         // 0..15
    int laneB_koff = ((lid >> 3) & 1) * 16;              // 0 or 16 bytes

    float c[2][8][4];
#pragma unroll
    for (int t = 0; t < 2; t++)
#pragma unroll
        for (int q = 0; q < 8; q++)
#pragma unroll
            for (int j = 0; j < 4; j++) c[t][q][j] = 0.f;

    auto load_stage = [&](int buf, int kc) {
        uint32_t abase = sb + buf * STAGE_BYTES;
        uint32_t bbase = abase + A_BYTES;
        int k0 = kc * BK;
#pragma unroll
        for (int t = 0; t < 4; t++) {
            int idx = t * THREADS + tid;
            int r = idx >> 3, j = idx & 7;
            cp16(abase + SW128(r * 128 + j * 16),
                 A + (size_t)(m0 + r) * DIN + k0 + j * 8);
        }
#pragma unroll
        for (int t = 0; t < 4; t++) {
            int idx = t * THREADS + tid;
            int r = idx >> 3, j = idx & 7;
            cp16(bbase + SW128(r * 128 + j * 16),
                 Bw + (size_t)(n0 + r) * DIN + k0 + j * 8);
        }
        asm volatile("cp.async.commit_group;" ::: "memory");
    };

    load_stage(0, 0);
    load_stage(1, 1);

    for (int i = 0; i < KITERS; i++) {
        int buf = i % NSTAGE;
        if (i < KITERS - 1)
            asm volatile("cp.async.wait_group 1;" ::: "memory");
        else
            asm volatile("cp.async.wait_group 0;" ::: "memory");
        __syncthreads();

        if (i + 2 < KITERS) load_stage((i + 2) % NSTAGE, i + 2);

        uint32_t aS = sb + buf * STAGE_BYTES;
        uint32_t bS = aS + A_BYTES;
#pragma unroll
        for (int kk = 0; kk < 4; kk++) {
            uint32_t afrag[2][4];
#pragma unroll
            for (int t = 0; t < 2; t++) {
                int row = wm * 32 + t * 16 + laneA_row;
                ldsm4(afrag[t][0], afrag[t][1], afrag[t][2], afrag[t][3],
                      aS + SW128(row * 128 + kk * 32 + laneA_koff));
            }
#pragma unroll
            for (int p = 0; p < 4; p++) {
                int row = wn * 64 + p * 16 + laneB_row;
                uint32_t r0, r1, r2, r3;
                ldsm4(r0, r1, r2, r3,
                      bS + SW128(row * 128 + kk * 32 + laneB_koff));
                uint32_t b0[2] = {r0, r1}, b1[2] = {r2, r3};
#pragma unroll
                for (int t = 0; t < 2; t++) {
                    mma16816(c[t][2 * p], afrag[t], b0);
                    mma16816(c[t][2 * p + 1], afrag[t], b1);
                }
            }
        }
    }

    // ---- epilogue: fused bias + float2 stores ----
    int ncol0 = n0 + wn * 64 + (lid & 3) * 2;
    float2 bb[8];
#pragma unroll
    for (int q = 0; q < 8; q++)
        bb[q] = *reinterpret_cast<const float2*>(bias + ncol0 + q * 8);

#pragma unroll
    for (int t = 0; t < 2; t++) {
#pragma unroll
        for (int h = 0; h < 2; h++) {
            int m = m0 + wm * 32 + t * 16 + h * 8 + (lid >> 2);
            float* orow = out + (size_t)m * DOUT;
#pragma unroll
            for (int q = 0; q < 8; q++) {
                float2 vo;
                vo.x = c[t][q][2 * h + 0] + bb[q].x;
                vo.y = c[t][q][2 * h + 1] + bb[q].y;
                *reinterpret_cast<float2*>(orow + ncol0 + q * 8) = vo;
            }
        }
    }
}

// ============================ launch ============================
extern "C" void kernel_launch(void* const* d_in, const int* in_sizes, int n_in,
                              void* d_out, int out_size) {
    const float* x    = (const float*)d_in[0];
    const float* w    = (const float*)d_in[1];
    const float* bias = (const float*)d_in[2];
    float* out = (float*)d_out;
    int M = in_sizes[0] / DIN;   // 65536

    __nv_bfloat16 *xq, *wq;
    cudaGetSymbolAddress((void**)&xq, g_xq);
    cudaGetSymbolAddress((void**)&wq, g_wq);

    // single fused quant launch: x warps first, then w warps (128 float4/warp)
    int xwarps = (M * DIN / 4) / 128;          // 131072
    int wwarps = (DOUT * DIN / 4) / 128;       // 2048
    int qblocks = (xwarps + wwarps) / 8;       // 8 warps per 256-thr block
    quant_fused_kernel<<<qblocks, 256>>>((const float4*)x, (uint2*)xq,
                                         (const float4*)w, (uint2*)wq, xwarps);

    cudaFuncSetAttribute(gemm_kernel, cudaFuncAttributeMaxDynamicSharedMemorySize,
                         SMEM_TOTAL);
    dim3 grid(DOUT / BN, M / BM);   // (8, 512)
    gemm_kernel<<<grid, THREADS, SMEM_TOTAL>>>(xq, wq, bias, out);
}